// round 16
// baseline (speedup 1.0000x reference)
#include <cuda_runtime.h>

#define ALPHA_F 0.1f

constexpr int Bb  = 32;
constexpr int Tt  = 2048;
constexpr int DIN = 128;
constexpr int Hh  = 512;
constexpr int CHUNK = 128;
constexpr int NCH  = Tt / CHUNK;
constexpr int NW   = Tt / 2;              // 1024 pair-iterations

__device__ float g_xproj[(size_t)Bb * Tt * Hh];
__device__ int g_cnt[Bb][NCH];

#define PACK2(d, lo, hi)   asm("mov.b64 %0, {%1, %2};" : "=l"(d) : "f"(lo), "f"(hi))
#define UNPACK2(lo, hi, s) asm("mov.b64 {%0, %1}, %2;" : "=f"(lo), "=f"(hi) : "l"(s))
#define FMA2(d, a, b)      asm("fma.rn.f32x2 %0, %1, %2, %0;" : "+l"(d) : "l"(a), "l"(b))

__device__ __forceinline__ float tanh_fast(float x) {
    float y;
    asm("tanh.approx.f32 %0, %1;" : "=f"(y) : "f"(x));
    return y;
}

constexpr float FXSCALE = 1048576.0f;        // 2^20 (A sums / delta domain)
constexpr float FXINV   = 1.0f / 1048576.0f;
constexpr float CSCALE  = 16777216.0f;       // 2^24 (C sums)
constexpr float CINV    = 1.0f / 16777216.0f;
constexpr float MAGICF  = 12582912.0f;       // 1.5*2^23
constexpr unsigned MAGICU = 0x4B400000u;
constexpr unsigned BIAS_FIX = (unsigned)(127u * MAGICU);  // mod 2^32
constexpr float MCC = -MAGICF * CINV;        // exact -0.75

constexpr int BM = 128, BN = 128, BK = 32;

__global__ void zero_cnt_kernel() {
    int i = threadIdx.x;
    if (i < Bb * NCH) ((int*)g_cnt)[i] = 0;
}

__device__ __forceinline__ void wait_chunk(int b, int c) {
    volatile int* p = &g_cnt[b][c];
    if (*p < 4) {
        while (*p < 4) __nanosleep(64);
    }
    __threadfence();
}

// =====================================================================
// Fused kernel (occ=1): blocks [0,32) scan (private SMs), rest proj.
// Scan: linearized with LAG-2 pipeline. At iteration i (steps 2i,2i+1):
//  consume: A-pair + C posted at iteration i-2 (anchored at then-exact h),
//           output trajectories wOut posted then, delta carried from i-1.
//  compute: scalar 2x2 affine maps -> S, delta; outputs h = w + am*delta.
//  post: anchor = h[2i+1]; roll pure trajectory w 4 steps; A at rolls 2,3;
//        C at anchor; REDUX results consumed at i+2 (latency hidden).
// =====================================================================
__global__ __launch_bounds__(256, 1) void fused_kernel(const float* __restrict__ X,
                                                       const float* __restrict__ Iw,
                                                       const float* __restrict__ mw,
                                                       const float* __restrict__ nw,
                                                       float* __restrict__ out) {
    __shared__ float As[BK][BM + 4];
    __shared__ float Bs[BK][BN + 4];
    __shared__ int4  wsum[4][4][2];   // [buf][warp][{A: Aa0,Aa1,Ab0,Ab1},{C}]

    const int bid = blockIdx.x;

    if (bid >= Bb) {
        // ================= PROJ TILE (unchanged) =================
        const int pbid = bid - Bb;
        const int tc   = pbid >> 7;
        const int rem  = pbid & 127;
        const int b    = rem >> 2;
        const int nc   = rem & 3;
        const long long m0 = (long long)b * Tt + (long long)tc * CHUNK;
        const int       n0 = nc * BN;

        const int tid = threadIdx.x;
        const int tx  = tid & 15;
        const int ty  = tid >> 4;

        unsigned long long acc[8][4];
#pragma unroll
        for (int i = 0; i < 8; i++)
#pragma unroll
            for (int j = 0; j < 4; j++) acc[i][j] = 0ull;

        for (int kt = 0; kt < DIN; kt += BK) {
#pragma unroll
            for (int q = 0; q < 4; q++) {
                int p   = tid + q * 256;
                int row = p >> 3;
                int kq  = p & 7;
                float4 av = *(const float4*)(X + (m0 + row) * DIN + kt + kq * 4);
                As[kq * 4 + 0][row] = av.x; As[kq * 4 + 1][row] = av.y;
                As[kq * 4 + 2][row] = av.z; As[kq * 4 + 3][row] = av.w;
                float4 bv = *(const float4*)(Iw + (long long)(n0 + row) * DIN + kt + kq * 4);
                Bs[kq * 4 + 0][row] = ALPHA_F * bv.x; Bs[kq * 4 + 1][row] = ALPHA_F * bv.y;
                Bs[kq * 4 + 2][row] = ALPHA_F * bv.z; Bs[kq * 4 + 3][row] = ALPHA_F * bv.w;
            }
            __syncthreads();

#pragma unroll
            for (int k = 0; k < BK; k++) {
                float4 a0 = *(const float4*)&As[k][ty * 8];
                float4 a1 = *(const float4*)&As[k][ty * 8 + 4];
                const unsigned long long* bp =
                    (const unsigned long long*)&Bs[k][tx * 8];
                unsigned long long pb0 = bp[0], pb1 = bp[1], pb2 = bp[2], pb3 = bp[3];
                float av[8] = {a0.x, a0.y, a0.z, a0.w, a1.x, a1.y, a1.z, a1.w};
#pragma unroll
                for (int i = 0; i < 8; i++) {
                    unsigned long long pa;
                    PACK2(pa, av[i], av[i]);
                    FMA2(acc[i][0], pa, pb0);
                    FMA2(acc[i][1], pa, pb1);
                    FMA2(acc[i][2], pa, pb2);
                    FMA2(acc[i][3], pa, pb3);
                }
            }
            __syncthreads();
        }

#pragma unroll
        for (int i = 0; i < 8; i++) {
            float4 o0, o1;
            UNPACK2(o0.x, o0.y, acc[i][0]);
            UNPACK2(o0.z, o0.w, acc[i][1]);
            UNPACK2(o1.x, o1.y, acc[i][2]);
            UNPACK2(o1.z, o1.w, acc[i][3]);
            long long row = m0 + ty * 8 + i;
            float* op = g_xproj + row * Hh + n0 + tx * 8;
            *(float4*)op       = o0;
            *(float4*)(op + 4) = o1;
        }

        __threadfence();
        __syncthreads();
        if (tid == 0) atomicAdd(&g_cnt[b][tc], 1);
        return;
    }

    // ================= SCAN =================
    if (threadIdx.x >= 128) return;

    const int b    = bid;
    const int tid  = threadIdx.x;
    const int wid  = tid >> 5;
    const int lane = tid & 31;
    const int i0   = tid * 4;

    // constants
    float am0[4], am1[4];                 // alpha*m * 2^-20 (outputs)
    float amr0[4], amr1[4];               // alpha*m (C partials)
    unsigned long long n00[4], n11[4], n24[4];
#pragma unroll
    for (int j = 0; j < 4; j++) {
        float m0v = mw[(i0 + j) * 2 + 0], m1v = mw[(i0 + j) * 2 + 1];
        float n0v = nw[(i0 + j) * 2 + 0], n1v = nw[(i0 + j) * 2 + 1];
        am0[j]  = (ALPHA_F * FXINV) * m0v;
        am1[j]  = (ALPHA_F * FXINV) * m1v;
        amr0[j] = ALPHA_F * m0v;
        amr1[j] = ALPHA_F * m1v;
        PACK2(n00[j], FXSCALE * n0v, FXSCALE * n0v);
        PACK2(n11[j], FXSCALE * n1v, FXSCALE * n1v);
        PACK2(n24[j], CSCALE * n0v, CSCALE * n1v);
    }

    const float4* xp4  = (const float4*)(g_xproj + (size_t)b * Tt * Hh);
    float*        outb = out + (size_t)b * Tt * Hh;

    // partial dots + 8 REDUX + post into wsum[buf]
    // ta/tb = tanh at the two A-arg trajectories; tha = tanh at anchor (for C)
    auto post_sums = [&](int buf, const float* ta, const float* tb, const float* tha) {
        unsigned long long A0 = 0ull, A1 = 0ull, Cp0 = 0ull, Cp1 = 0ull;
#pragma unroll
        for (int j = 0; j < 4; j++) {
            unsigned long long tp;
            PACK2(tp, ta[j], tb[j]);
            FMA2(A0, tp, n00[j]);                 // (Aa0, Ab0)
            FMA2(A1, tp, n11[j]);                 // (Aa1, Ab1)
            float d  = fmaf(-tha[j], tha[j], 1.0f);
            float c0 = amr0[j] * d, c1 = amr1[j] * d;
            unsigned long long p0, p1;
            PACK2(p0, c0, c0);
            FMA2(Cp0, p0, n24[j]);                // (C00, C10)
            PACK2(p1, c1, c1);
            FMA2(Cp1, p1, n24[j]);                // (C01, C11)
        }
        float aa0, ab0, aa1, ab1, c00, c10, c01, c11;
        UNPACK2(aa0, ab0, A0);
        UNPACK2(aa1, ab1, A1);
        UNPACK2(c00, c10, Cp0);
        UNPACK2(c01, c11, Cp1);
        unsigned q0 = __reduce_add_sync(0xffffffffu, __float_as_uint(aa0 + MAGICF));
        unsigned q1 = __reduce_add_sync(0xffffffffu, __float_as_uint(aa1 + MAGICF));
        unsigned q2 = __reduce_add_sync(0xffffffffu, __float_as_uint(ab0 + MAGICF));
        unsigned q3 = __reduce_add_sync(0xffffffffu, __float_as_uint(ab1 + MAGICF));
        unsigned q4 = __reduce_add_sync(0xffffffffu, __float_as_uint(c00 + MAGICF));
        unsigned q5 = __reduce_add_sync(0xffffffffu, __float_as_uint(c01 + MAGICF));
        unsigned q6 = __reduce_add_sync(0xffffffffu, __float_as_uint(c10 + MAGICF));
        unsigned q7 = __reduce_add_sync(0xffffffffu, __float_as_uint(c11 + MAGICF));
        if (lane == 0) {
            wsum[buf][wid][0] = make_int4((int)q0, (int)q1, (int)q2, (int)q3);
            wsum[buf][wid][1] = make_int4((int)q4, (int)q5, (int)q6, (int)q7);
        }
    };

    // xp ring: pair k = rows (2k, 2k+1) in slot k&3
    float4 xrA[4], xrB[4];
    float4 wOutA[2], wOutB[2];

    wait_chunk(b, 0);
#pragma unroll
    for (int k = 0; k < 4; k++) {
        xrA[k] = xp4[(size_t)(2 * k) * 128 + tid];
        xrB[k] = xp4[(size_t)(2 * k + 1) * 128 + tid];
    }

    // ---- prologue: post windows 0 and 1, both anchored at h[-1] = 0 ----
    {
        // window 0 (buf 0): tanh args w[-1]=0, w[0]=xp0; C at 0; traj w[0],w[1]
        float4 w1 = xrA[0];
        float4 w2 = make_float4(fmaf(0.9f, w1.x, xrB[0].x), fmaf(0.9f, w1.y, xrB[0].y),
                                fmaf(0.9f, w1.z, xrB[0].z), fmaf(0.9f, w1.w, xrB[0].w));
        float z4[4] = {0.f, 0.f, 0.f, 0.f};
        float tb[4] = {tanh_fast(w1.x), tanh_fast(w1.y), tanh_fast(w1.z), tanh_fast(w1.w)};
        post_sums(0, z4, tb, z4);
        wOutA[0] = w1; wOutB[0] = w2;

        // window 1 (buf 1): tanh args w[1], w[2]; C at 0; traj w[2], w[3]
        float4 w3 = make_float4(fmaf(0.9f, w2.x, xrA[1].x), fmaf(0.9f, w2.y, xrA[1].y),
                                fmaf(0.9f, w2.z, xrA[1].z), fmaf(0.9f, w2.w, xrA[1].w));
        float4 w4 = make_float4(fmaf(0.9f, w3.x, xrB[1].x), fmaf(0.9f, w3.y, xrB[1].y),
                                fmaf(0.9f, w3.z, xrB[1].z), fmaf(0.9f, w3.w, xrB[1].w));
        float ta2[4] = {tanh_fast(w2.x), tanh_fast(w2.y), tanh_fast(w2.z), tanh_fast(w2.w)};
        float tb2[4] = {tanh_fast(w3.x), tanh_fast(w3.y), tanh_fast(w3.z), tanh_fast(w3.w)};
        post_sums(1, ta2, tb2, z4);
        wOutA[1] = w3; wOutB[1] = w4;
    }
    __syncthreads();

    float dh0 = 0.f, dh1 = 0.f;      // delta carried (fx 2^20 units)
    float* optr = outb + i0;

    // ---------------- main loop: 2 timesteps / iteration ----------------
    for (int i = 0; i < NW; i++) {
        const int buf = i & 3;
        const int sl  = i & 1;

        // combine (posted at i-2, already barred: no wait)
        int4 u0 = wsum[buf][0][0], u1 = wsum[buf][1][0];
        int4 u2 = wsum[buf][2][0], u3 = wsum[buf][3][0];
        int4 v0 = wsum[buf][0][1], v1 = wsum[buf][1][1];
        int4 v2 = wsum[buf][2][1], v3 = wsum[buf][3][1];
        float Aa0 = __uint_as_float((unsigned)(u0.x + u1.x + u2.x + u3.x) - BIAS_FIX) - MAGICF;
        float Aa1 = __uint_as_float((unsigned)(u0.y + u1.y + u2.y + u3.y) - BIAS_FIX) - MAGICF;
        float Ab0 = __uint_as_float((unsigned)(u0.z + u1.z + u2.z + u3.z) - BIAS_FIX) - MAGICF;
        float Ab1 = __uint_as_float((unsigned)(u0.w + u1.w + u2.w + u3.w) - BIAS_FIX) - MAGICF;
        float C00 = fmaf(__uint_as_float((unsigned)(v0.x + v1.x + v2.x + v3.x) - BIAS_FIX), CINV, MCC);
        float C01 = fmaf(__uint_as_float((unsigned)(v0.y + v1.y + v2.y + v3.y) - BIAS_FIX), CINV, MCC);
        float C10 = fmaf(__uint_as_float((unsigned)(v0.z + v1.z + v2.z + v3.z) - BIAS_FIX), CINV, MCC);
        float C11 = fmaf(__uint_as_float((unsigned)(v0.w + v1.w + v2.w + v3.w) - BIAS_FIX), CINV, MCC);

        // prefetch pair p_{i+4} (rows 2i+8, 2i+9) into slot i&3 (dead slot)
        {
            int r = 2 * i + 8;
            if (r < Tt) {
                if ((r & (CHUNK - 1)) == 0) wait_chunk(b, r >> 7);
                xrA[buf & 3] = xp4[(size_t)r * 128 + tid];
                xrB[buf & 3] = xp4[(size_t)(r + 1) * 128 + tid];
            }
        }

        // scalar affine maps (delta/S in fx units, rel. this window's anchor)
        float S0a = fmaf(C00, dh0, fmaf(C01, dh1, Aa0));
        float S1a = fmaf(C10, dh0, fmaf(C11, dh1, Aa1));
        float d0p = fmaf(0.9f, dh0, S0a);
        float d1p = fmaf(0.9f, dh1, S1a);
        float S0b = fmaf(C00, d0p, fmaf(C01, d1p, Ab0));
        float S1b = fmaf(C10, d0p, fmaf(C11, d1p, Ab1));
        float d0q = fmaf(0.9f, d0p, S0b);
        float d1q = fmaf(0.9f, d1p, S1b);
        dh0 = fmaf(0.9f, S0a, S0b);        // handoff: delta rel. NEW anchor h[2i-1]->h[2i+1]
        dh1 = fmaf(0.9f, S1a, S1b);

        // outputs: h = w + am*delta
        float4 wA = wOutA[sl], wB = wOutB[sl];
        float4 hA, hB;
        hA.x = fmaf(am0[0], d0p, fmaf(am1[0], d1p, wA.x));
        hA.y = fmaf(am0[1], d0p, fmaf(am1[1], d1p, wA.y));
        hA.z = fmaf(am0[2], d0p, fmaf(am1[2], d1p, wA.z));
        hA.w = fmaf(am0[3], d0p, fmaf(am1[3], d1p, wA.w));
        hB.x = fmaf(am0[0], d0q, fmaf(am1[0], d1q, wB.x));
        hB.y = fmaf(am0[1], d0q, fmaf(am1[1], d1q, wB.y));
        hB.z = fmaf(am0[2], d0q, fmaf(am1[2], d1q, wB.z));
        hB.w = fmaf(am0[3], d0q, fmaf(am1[3], d1q, wB.w));
        *(float4*)optr        = hA;
        *(float4*)(optr + Hh) = hB;
        optr += 2 * Hh;

        // post for window i+2 (anchor = h[2i+1] = hB), REDUX consumed at i+2
        if (i < NW - 2) {
            const int ra = (i + 1) & 3, rb = (i + 2) & 3;
            float tha[4] = {tanh_fast(hB.x), tanh_fast(hB.y),
                            tanh_fast(hB.z), tanh_fast(hB.w)};
            float4 w1, w2, w3, w4;
            w1.x = fmaf(0.9f, hB.x, xrA[ra].x); w1.y = fmaf(0.9f, hB.y, xrA[ra].y);
            w1.z = fmaf(0.9f, hB.z, xrA[ra].z); w1.w = fmaf(0.9f, hB.w, xrA[ra].w);
            w2.x = fmaf(0.9f, w1.x, xrB[ra].x); w2.y = fmaf(0.9f, w1.y, xrB[ra].y);
            w2.z = fmaf(0.9f, w1.z, xrB[ra].z); w2.w = fmaf(0.9f, w1.w, xrB[ra].w);
            w3.x = fmaf(0.9f, w2.x, xrA[rb].x); w3.y = fmaf(0.9f, w2.y, xrA[rb].y);
            w3.z = fmaf(0.9f, w2.z, xrA[rb].z); w3.w = fmaf(0.9f, w2.w, xrA[rb].w);
            w4.x = fmaf(0.9f, w3.x, xrB[rb].x); w4.y = fmaf(0.9f, w3.y, xrB[rb].y);
            w4.z = fmaf(0.9f, w3.z, xrB[rb].z); w4.w = fmaf(0.9f, w3.w, xrB[rb].w);
            float ta[4] = {tanh_fast(w2.x), tanh_fast(w2.y),
                           tanh_fast(w2.z), tanh_fast(w2.w)};
            float tb[4] = {tanh_fast(w3.x), tanh_fast(w3.y),
                           tanh_fast(w3.z), tanh_fast(w3.w)};
            post_sums((i + 2) & 3, ta, tb, tha);
            wOutA[sl] = w3;   // output trajectories for window i+2
            wOutB[sl] = w4;
        }
        __syncthreads();
    }
}

// =====================================================================
extern "C" void kernel_launch(void* const* d_in, const int* in_sizes, int n_in,
                              void* d_out, int out_size) {
    const float* x  = (const float*)d_in[0];  // [32, 2048, 128]
    const float* m  = (const float*)d_in[1];  // [512, 2]
    const float* n  = (const float*)d_in[2];  // [512, 2]
    const float* Iw = (const float*)d_in[3];  // [512, 128]
    float* out = (float*)d_out;               // [32, 2048, 512]

    zero_cnt_kernel<<<1, 512>>>();
    fused_kernel<<<Bb + (Bb * NCH * 4), 256>>>(x, Iw, m, n, out);
}

// round 17
// speedup vs baseline: 1.6231x; 1.6231x over previous
#include <cuda_runtime.h>

#define ALPHA_F 0.1f

constexpr int Bb  = 32;
constexpr int Tt  = 2048;
constexpr int DIN = 128;
constexpr int Hh  = 512;
constexpr int CHUNK = 128;
constexpr int NCH  = Tt / CHUNK;

__device__ float g_xproj[(size_t)Bb * Tt * Hh];
__device__ int g_cnt[Bb][NCH];

#define PACK2(d, lo, hi)   asm("mov.b64 %0, {%1, %2};" : "=l"(d) : "f"(lo), "f"(hi))
#define UNPACK2(lo, hi, s) asm("mov.b64 {%0, %1}, %2;" : "=f"(lo), "=f"(hi) : "l"(s))
#define FMA2(d, a, b)      asm("fma.rn.f32x2 %0, %1, %2, %0;" : "+l"(d) : "l"(a), "l"(b))

__device__ __forceinline__ float tanh_fast(float x) {
    float y;
    asm("tanh.approx.f32 %0, %1;" : "=f"(y) : "f"(x));
    return y;
}

constexpr float FXSCALE = 1048576.0f;        // 2^20 (A sums / S domain)
constexpr float FXINV   = 1.0f / 1048576.0f;
constexpr float CSCALE  = 16777216.0f;       // 2^24 (C sums)
constexpr float CINV    = 1.0f / 16777216.0f;
constexpr float MAGICF  = 12582912.0f;       // 1.5*2^23
constexpr unsigned MAGICU = 0x4B400000u;
constexpr unsigned BIAS_FIX = (unsigned)(255u * MAGICU);  // 256 lanes, mod 2^32
constexpr float MCC = -MAGICF * CINV;        // exact -0.75

constexpr int BM = 128, BN = 128, BK = 32;

__global__ void zero_cnt_kernel() {
    int i = threadIdx.x;
    if (i < Bb * NCH) ((int*)g_cnt)[i] = 0;
}

__device__ __forceinline__ void wait_chunk(int b, int c) {
    volatile int* p = &g_cnt[b][c];
    if (*p < 4) {
        while (*p < 4) __nanosleep(64);
    }
    __threadfence();
}

// =====================================================================
// Fused kernel (occ=1): blocks [0,32) scan (private SMs), rest proj.
// Scan: R14 linearized 2-steps-per-barrier structure, now with ALL 8
// warps (256 threads, 2 h per thread): per-thread serial work halved.
//   A(w)=n·tanh(w) for w=u,v jointly (packed f32x2)
//   C = n·(am)·(1-tanh(u)^2) once per pair
// 8 REDUX/pair, S advances via scalar 2x2 affine maps.
// =====================================================================
__global__ __launch_bounds__(256, 1) void fused_kernel(const float* __restrict__ X,
                                                       const float* __restrict__ Iw,
                                                       const float* __restrict__ mw,
                                                       const float* __restrict__ nw,
                                                       float* __restrict__ out) {
    __shared__ float As[BK][BM + 4];
    __shared__ float Bs[BK][BN + 4];
    __shared__ int4  wsum[2][8];   // [parity][warp] = (Au0,Au1,Av0,Av1)
    __shared__ int4  csum[2][8];   // [parity][warp] = (C00,C01,C10,C11)

    const int bid = blockIdx.x;

    if (bid >= Bb) {
        // ================= PROJ TILE (unchanged) =================
        const int pbid = bid - Bb;
        const int tc   = pbid >> 7;
        const int rem  = pbid & 127;
        const int b    = rem >> 2;
        const int nc   = rem & 3;
        const long long m0 = (long long)b * Tt + (long long)tc * CHUNK;
        const int       n0 = nc * BN;

        const int tid = threadIdx.x;
        const int tx  = tid & 15;
        const int ty  = tid >> 4;

        unsigned long long acc[8][4];
#pragma unroll
        for (int i = 0; i < 8; i++)
#pragma unroll
            for (int j = 0; j < 4; j++) acc[i][j] = 0ull;

        for (int kt = 0; kt < DIN; kt += BK) {
#pragma unroll
            for (int q = 0; q < 4; q++) {
                int p   = tid + q * 256;
                int row = p >> 3;
                int kq  = p & 7;
                float4 av = *(const float4*)(X + (m0 + row) * DIN + kt + kq * 4);
                As[kq * 4 + 0][row] = av.x; As[kq * 4 + 1][row] = av.y;
                As[kq * 4 + 2][row] = av.z; As[kq * 4 + 3][row] = av.w;
                float4 bv = *(const float4*)(Iw + (long long)(n0 + row) * DIN + kt + kq * 4);
                Bs[kq * 4 + 0][row] = ALPHA_F * bv.x; Bs[kq * 4 + 1][row] = ALPHA_F * bv.y;
                Bs[kq * 4 + 2][row] = ALPHA_F * bv.z; Bs[kq * 4 + 3][row] = ALPHA_F * bv.w;
            }
            __syncthreads();

#pragma unroll
            for (int k = 0; k < BK; k++) {
                float4 a0 = *(const float4*)&As[k][ty * 8];
                float4 a1 = *(const float4*)&As[k][ty * 8 + 4];
                const unsigned long long* bp =
                    (const unsigned long long*)&Bs[k][tx * 8];
                unsigned long long pb0 = bp[0], pb1 = bp[1], pb2 = bp[2], pb3 = bp[3];
                float av[8] = {a0.x, a0.y, a0.z, a0.w, a1.x, a1.y, a1.z, a1.w};
#pragma unroll
                for (int i = 0; i < 8; i++) {
                    unsigned long long pa;
                    PACK2(pa, av[i], av[i]);
                    FMA2(acc[i][0], pa, pb0);
                    FMA2(acc[i][1], pa, pb1);
                    FMA2(acc[i][2], pa, pb2);
                    FMA2(acc[i][3], pa, pb3);
                }
            }
            __syncthreads();
        }

#pragma unroll
        for (int i = 0; i < 8; i++) {
            float4 o0, o1;
            UNPACK2(o0.x, o0.y, acc[i][0]);
            UNPACK2(o0.z, o0.w, acc[i][1]);
            UNPACK2(o1.x, o1.y, acc[i][2]);
            UNPACK2(o1.z, o1.w, acc[i][3]);
            long long row = m0 + ty * 8 + i;
            float* op = g_xproj + row * Hh + n0 + tx * 8;
            *(float4*)op       = o0;
            *(float4*)(op + 4) = o1;
        }

        __threadfence();
        __syncthreads();
        if (tid == 0) atomicAdd(&g_cnt[b][tc], 1);
        return;
    }

    // ================= SCAN (256 threads, 2 h each) =================
    const int b    = bid;
    const int tid  = threadIdx.x;
    const int wid  = tid >> 5;
    const int lane = tid & 31;
    const int i0   = tid * 2;

    // constants (2 elements per thread)
    float am0[2], am1[2];
    float amr0[2], amr1[2];
    unsigned long long n00[2], n11[2], n24[2];
#pragma unroll
    for (int j = 0; j < 2; j++) {
        float m0v = mw[(i0 + j) * 2 + 0], m1v = mw[(i0 + j) * 2 + 1];
        float n0v = nw[(i0 + j) * 2 + 0], n1v = nw[(i0 + j) * 2 + 1];
        am0[j]  = (ALPHA_F * FXINV) * m0v;
        am1[j]  = (ALPHA_F * FXINV) * m1v;
        amr0[j] = ALPHA_F * m0v;
        amr1[j] = ALPHA_F * m1v;
        PACK2(n00[j], FXSCALE * n0v, FXSCALE * n0v);
        PACK2(n11[j], FXSCALE * n1v, FXSCALE * n1v);
        PACK2(n24[j], CSCALE * n0v, CSCALE * n1v);
    }

    const float2* xp2  = (const float2*)(g_xproj + (size_t)b * Tt * Hh);
    float*        outb = out + (size_t)b * Tt * Hh;
    const int ROW2 = Hh / 2;   // 256 float2 per row

    // partials + 8 REDUX + post: A for u&v (joint), C from u's tanh
    auto reduce_post = [&](int parity, const float* uw, const float* vw) {
        unsigned long long Ap0 = 0ull, Ap1 = 0ull, Cp0 = 0ull, Cp1 = 0ull;
        float thU[2];
#pragma unroll
        for (int j = 0; j < 2; j++) {
            thU[j]   = tanh_fast(uw[j]);
            float tv = tanh_fast(vw[j]);
            unsigned long long tp;
            PACK2(tp, thU[j], tv);
            FMA2(Ap0, tp, n00[j]);               // (Au0, Av0)
            FMA2(Ap1, tp, n11[j]);               // (Au1, Av1)
        }
#pragma unroll
        for (int j = 0; j < 2; j++) {
            float d  = fmaf(-thU[j], thU[j], 1.0f);
            float w0 = amr0[j] * d, w1 = amr1[j] * d;
            unsigned long long p0, p1;
            PACK2(p0, w0, w0);
            FMA2(Cp0, p0, n24[j]);               // (C00, C10)
            PACK2(p1, w1, w1);
            FMA2(Cp1, p1, n24[j]);               // (C01, C11)
        }
        float au0, av0, au1, av1, c00, c10, c01, c11;
        UNPACK2(au0, av0, Ap0);
        UNPACK2(au1, av1, Ap1);
        UNPACK2(c00, c10, Cp0);
        UNPACK2(c01, c11, Cp1);
        unsigned q0 = __reduce_add_sync(0xffffffffu, __float_as_uint(au0 + MAGICF));
        unsigned q1 = __reduce_add_sync(0xffffffffu, __float_as_uint(au1 + MAGICF));
        unsigned q2 = __reduce_add_sync(0xffffffffu, __float_as_uint(av0 + MAGICF));
        unsigned q3 = __reduce_add_sync(0xffffffffu, __float_as_uint(av1 + MAGICF));
        unsigned q4 = __reduce_add_sync(0xffffffffu, __float_as_uint(c00 + MAGICF));
        unsigned q5 = __reduce_add_sync(0xffffffffu, __float_as_uint(c01 + MAGICF));
        unsigned q6 = __reduce_add_sync(0xffffffffu, __float_as_uint(c10 + MAGICF));
        unsigned q7 = __reduce_add_sync(0xffffffffu, __float_as_uint(c11 + MAGICF));
        if (lane == 0) {
            wsum[parity][wid] = make_int4((int)q0, (int)q1, (int)q2, (int)q3);
            csum[parity][wid] = make_int4((int)q4, (int)q5, (int)q6, (int)q7);
        }
    };

    // ---------------- prologue ----------------
    wait_chunk(b, 0);
    float2 r0 = xp2[0 * ROW2 + tid];
    float2 r1 = xp2[1 * ROW2 + tid];
    float2 ringA[2], ringB[2];
    ringA[0] = xp2[2 * ROW2 + tid]; ringB[0] = xp2[3 * ROW2 + tid];
    ringA[1] = xp2[4 * ROW2 + tid]; ringB[1] = xp2[5 * ROW2 + tid];

    float ua[2] = {r0.x, r0.y};                  // u_0 (h0 = 0; xp pre-scaled)
    float vb[2];
    vb[0] = fmaf(0.9f, ua[0], r1.x);
    vb[1] = fmaf(0.9f, ua[1], r1.y);             // v_1

    reduce_post(0, ua, vb);
    __syncthreads();

    float S0 = 0.f, S1 = 0.f;                    // S-hat (x 2^20)
    float* optr = outb + i0;
    int    pref_row = 6;

    // ---------------- main loop: 2 timesteps / iteration ----------------
#pragma unroll 2
    for (int i = 0; i < Tt / 2; i++) {
        const int p = i & 1;

        // combine previous pair's reductions (8 warps)
        int4 a0 = wsum[p][0], a1 = wsum[p][1], a2 = wsum[p][2], a3 = wsum[p][3];
        int4 a4 = wsum[p][4], a5 = wsum[p][5], a6 = wsum[p][6], a7 = wsum[p][7];
        int4 c0 = csum[p][0], c1 = csum[p][1], c2 = csum[p][2], c3 = csum[p][3];
        int4 c4 = csum[p][4], c5 = csum[p][5], c6 = csum[p][6], c7 = csum[p][7];

        unsigned sAu0 = (unsigned)(((a0.x + a1.x) + (a2.x + a3.x)) +
                                   ((a4.x + a5.x) + (a6.x + a7.x))) - BIAS_FIX;
        unsigned sAu1 = (unsigned)(((a0.y + a1.y) + (a2.y + a3.y)) +
                                   ((a4.y + a5.y) + (a6.y + a7.y))) - BIAS_FIX;
        unsigned sAv0 = (unsigned)(((a0.z + a1.z) + (a2.z + a3.z)) +
                                   ((a4.z + a5.z) + (a6.z + a7.z))) - BIAS_FIX;
        unsigned sAv1 = (unsigned)(((a0.w + a1.w) + (a2.w + a3.w)) +
                                   ((a4.w + a5.w) + (a6.w + a7.w))) - BIAS_FIX;
        unsigned sC00 = (unsigned)(((c0.x + c1.x) + (c2.x + c3.x)) +
                                   ((c4.x + c5.x) + (c6.x + c7.x))) - BIAS_FIX;
        unsigned sC01 = (unsigned)(((c0.y + c1.y) + (c2.y + c3.y)) +
                                   ((c4.y + c5.y) + (c6.y + c7.y))) - BIAS_FIX;
        unsigned sC10 = (unsigned)(((c0.z + c1.z) + (c2.z + c3.z)) +
                                   ((c4.z + c5.z) + (c6.z + c7.z))) - BIAS_FIX;
        unsigned sC11 = (unsigned)(((c0.w + c1.w) + (c2.w + c3.w)) +
                                   ((c4.w + c5.w) + (c6.w + c7.w))) - BIAS_FIX;

        float fAu0 = __uint_as_float(sAu0) - MAGICF;
        float fAu1 = __uint_as_float(sAu1) - MAGICF;
        float fAv0 = __uint_as_float(sAv0) - MAGICF;
        float fAv1 = __uint_as_float(sAv1) - MAGICF;
        float C00 = fmaf(__uint_as_float(sC00), CINV, MCC);
        float C01 = fmaf(__uint_as_float(sC01), CINV, MCC);
        float C10 = fmaf(__uint_as_float(sC10), CINV, MCC);
        float C11 = fmaf(__uint_as_float(sC11), CINV, MCC);

        // h_{2i+1} = u + am*S (old S) -> out[2i]
        float he0 = fmaf(am0[0], S0, fmaf(am1[0], S1, ua[0]));
        float he1 = fmaf(am0[1], S0, fmaf(am1[1], S1, ua[1]));
        *(float2*)optr = make_float2(he0, he1);

        // scalar affine maps (one C matrix for both half-steps)
        float S0n = fmaf(C00, S0, fmaf(C01, S1, fAu0));   // S_{2i+1}
        float S1n = fmaf(C10, S0, fmaf(C11, S1, fAu1));
        float sv0 = fmaf(0.9f, S0, S0n);
        float sv1 = fmaf(0.9f, S1, S1n);
        float T0  = fmaf(C00, sv0, fmaf(C01, sv1, fAv0)); // S_{2i+2}
        float T1  = fmaf(C10, sv0, fmaf(C11, sv1, fAv1));

        // h_{2i+2} = v + am*sigma_v -> out[2i+1]
        float ho0 = fmaf(am0[0], sv0, fmaf(am1[0], sv1, vb[0]));
        float ho1 = fmaf(am0[1], sv0, fmaf(am1[1], sv1, vb[1]));
        *(float2*)(optr + Hh) = make_float2(ho0, ho1);
        optr += 2 * Hh;

        // consume + refill ring
        float2 xpA = ringA[p], xpB = ringB[p];
        {
            int ra = pref_row, rb = pref_row + 1;
            if (ra < Tt) {
                if ((ra & (CHUNK - 1)) == 0) wait_chunk(b, ra >> 7);
            } else ra = Tt - 1;
            if (rb >= Tt) rb = Tt - 1;
            ringA[p] = xp2[(size_t)ra * ROW2 + tid];
            ringB[p] = xp2[(size_t)rb * ROW2 + tid];
            pref_row += 2;
        }

        // u_{2i+2}, v_{2i+3}
        ua[0] = fmaf(0.9f, ho0, xpA.x); vb[0] = fmaf(0.9f, ua[0], xpB.x);
        ua[1] = fmaf(0.9f, ho1, xpA.y); vb[1] = fmaf(0.9f, ua[1], xpB.y);

        // reductions for next iteration
        reduce_post(p ^ 1, ua, vb);

        __syncthreads();
        S0 = T0; S1 = T1;
    }
}

// =====================================================================
extern "C" void kernel_launch(void* const* d_in, const int* in_sizes, int n_in,
                              void* d_out, int out_size) {
    const float* x  = (const float*)d_in[0];  // [32, 2048, 128]
    const float* m  = (const float*)d_in[1];  // [512, 2]
    const float* n  = (const float*)d_in[2];  // [512, 2]
    const float* Iw = (const float*)d_in[3];  // [512, 128]
    float* out = (float*)d_out;               // [32, 2048, 512]

    zero_cnt_kernel<<<1, 512>>>();
    fused_kernel<<<Bb + (Bb * NCH * 4), 256>>>(x, Iw, m, n, out);
}